// round 11
// baseline (speedup 1.0000x reference)
#include <cuda_runtime.h>

#define NN  100000      // nodes
#define FIN 512         // input features
#define HID 16          // hidden
#define NC  40          // classes
#define MAXE 4000000    // capacity for edge scratch
#define SCAN_B 512      // elems per scan block

// ---------------- device scratch --------------------------------------------
__device__ int   g_is64;
__device__ int   g_deg [NN];
__device__ int   g_scan[NN];
__device__ int   g_row [NN];
__device__ int   g_cur [NN];
__device__ int   g_bsum[256];
__device__ int   g_bpre[256];
__device__ float g_dinv[NN];
__device__ int   g_csr[MAXE];
__device__ float g_h [(size_t)NN * HID];   // raw x@W1 (side stream)
__device__ float g_hs[(size_t)NN * HID];   // h1*dinv, later a2
__device__ float g_ys[(size_t)NN * HID];   // relu(out1)*dinv

// ---------------- init: zero deg + detect index dtype -------------------------
__global__ __launch_bounds__(256) void init_k(const unsigned int* __restrict__ w,
                                              int E, int N) {
    int i = blockIdx.x * 256 + threadIdx.x;
    if (i < N) g_deg[i] = 0;
    if (blockIdx.x == 0) {
        __shared__ unsigned int sh[256];
        unsigned int acc = 0;
        int n = min(E, 4096);
        for (int j = threadIdx.x; j < n; j += 256) acc |= w[2 * j + 1];
        sh[threadIdx.x] = acc;
        __syncthreads();
        for (int s = 128; s > 0; s >>= 1) {
            if (threadIdx.x < s) sh[threadIdx.x] |= sh[threadIdx.x + s];
            __syncthreads();
        }
        if (threadIdx.x == 0) g_is64 = (sh[0] == 0u) ? 1 : 0;
    }
}

// ---------------- degree count ------------------------------------------------
__global__ __launch_bounds__(256) void count_deg(const void* __restrict__ ei, int E) {
    int e = blockIdx.x * 256 + threadIdx.x;
    if (e >= E) return;
    int d;
    if (g_is64) {
        const long long* p = (const long long*)ei;
        d = (int)p[e + E];
    } else {
        const int* p = (const int*)ei;
        d = p[e + E];
    }
    atomicAdd(&g_deg[d], 1);
}

// ---------------- prefix scan (3 kernels) -------------------------------------
__global__ __launch_bounds__(SCAN_B) void scan1(int N) {
    __shared__ int sh[SCAN_B];
    int gid = blockIdx.x * SCAN_B + threadIdx.x;
    int v = (gid < N) ? g_deg[gid] : 0;
    sh[threadIdx.x] = v;
    __syncthreads();
    for (int off = 1; off < SCAN_B; off <<= 1) {
        int t = (threadIdx.x >= off) ? sh[threadIdx.x - off] : 0;
        __syncthreads();
        sh[threadIdx.x] += t;
        __syncthreads();
    }
    if (gid < N) g_scan[gid] = sh[threadIdx.x];
    if (threadIdx.x == SCAN_B - 1) g_bsum[blockIdx.x] = sh[SCAN_B - 1];
}
__global__ __launch_bounds__(256) void scan2(int nblk) {
    __shared__ int sh[256];
    int v = (threadIdx.x < nblk) ? g_bsum[threadIdx.x] : 0;
    sh[threadIdx.x] = v;
    __syncthreads();
    for (int off = 1; off < 256; off <<= 1) {
        int t = (threadIdx.x >= off) ? sh[threadIdx.x - off] : 0;
        __syncthreads();
        sh[threadIdx.x] += t;
        __syncthreads();
    }
    g_bpre[threadIdx.x] = sh[threadIdx.x] - v;   // exclusive
}
__global__ __launch_bounds__(SCAN_B) void scan3(int N) {
    int gid = blockIdx.x * SCAN_B + threadIdx.x;
    if (gid >= N) return;
    int dg = g_deg[gid];
    int rs = g_scan[gid] - dg + g_bpre[blockIdx.x];
    g_row[gid] = rs;
    g_cur[gid] = rs;
    g_dinv[gid] = rsqrtf((float)(dg + 1));   // +1 self-loop
}

// ---------------- CSR fill ----------------------------------------------------
__global__ __launch_bounds__(256) void csr_fill(const void* __restrict__ ei, int E) {
    int e = blockIdx.x * 256 + threadIdx.x;
    if (e >= E) return;
    int s, d;
    if (g_is64) {
        const long long* p = (const long long*)ei;
        s = (int)p[e];
        d = (int)p[e + E];
    } else {
        const int* p = (const int*)ei;
        s = p[e];
        d = p[e + E];
    }
    int pos = atomicAdd(&g_cur[d], 1);
    g_csr[pos] = s;
}

// ---------------- packed f32x2 helpers ----------------------------------------
__device__ __forceinline__ unsigned long long pack2(float v) {
    unsigned long long r;
    unsigned int u = __float_as_uint(v);
    asm("mov.b64 %0, {%1, %1};" : "=l"(r) : "r"(u));
    return r;
}
__device__ __forceinline__ unsigned long long ffma2(unsigned long long a,
                                                    unsigned long long b,
                                                    unsigned long long c) {
    unsigned long long d;
    asm("fma.rn.f32x2 %0, %1, %2, %3;" : "=l"(d) : "l"(a), "l"(b), "l"(c));
    return d;
}
__device__ __forceinline__ float2 unpack2(unsigned long long v) {
    unsigned int lo, hi;
    asm("mov.b64 {%0, %1}, %2;" : "=r"(lo), "=r"(hi) : "l"(v));
    return make_float2(__uint_as_float(lo), __uint_as_float(hi));
}

// ---------------- GEMM1 (raw): h = x @ W1  (side stream) ----------------------
__global__ __launch_bounds__(128) void gemm1(const float* __restrict__ x,
                                             const float* __restrict__ W1, int N) {
    __shared__ ulonglong2 Ws[FIN * 4];   // 512 x 16 floats = 32KB
    const ulonglong2* Wg = (const ulonglong2*)W1;
    for (int i = threadIdx.x; i < FIN * 4; i += 128) Ws[i] = Wg[i];
    __syncthreads();

    int base = blockIdx.x * 512 + threadIdx.x * 4;
    if (base >= N) return;

    unsigned long long acc[4][8];
#pragma unroll
    for (int r = 0; r < 4; r++)
#pragma unroll
        for (int p = 0; p < 8; p++) acc[r][p] = 0ull;

    int row[4];
    const float* xp[4];
#pragma unroll
    for (int r = 0; r < 4; r++) {
        row[r] = min(base + r, N - 1);
        xp[r] = x + (size_t)row[r] * FIN;
    }

    for (int k = 0; k < FIN; k += 4) {
        float xv[4][4];
#pragma unroll
        for (int r = 0; r < 4; r++)
            *(float4*)xv[r] = *(const float4*)(xp[r] + k);
#pragma unroll
        for (int j = 0; j < 4; j++) {
            ulonglong2 wa = Ws[(k + j) * 4 + 0];
            ulonglong2 wb = Ws[(k + j) * 4 + 1];
            ulonglong2 wc = Ws[(k + j) * 4 + 2];
            ulonglong2 wd = Ws[(k + j) * 4 + 3];
#pragma unroll
            for (int r = 0; r < 4; r++) {
                unsigned long long px = pack2(xv[r][j]);
                acc[r][0] = ffma2(px, wa.x, acc[r][0]);
                acc[r][1] = ffma2(px, wa.y, acc[r][1]);
                acc[r][2] = ffma2(px, wb.x, acc[r][2]);
                acc[r][3] = ffma2(px, wb.y, acc[r][3]);
                acc[r][4] = ffma2(px, wc.x, acc[r][4]);
                acc[r][5] = ffma2(px, wc.y, acc[r][5]);
                acc[r][6] = ffma2(px, wd.x, acc[r][6]);
                acc[r][7] = ffma2(px, wd.y, acc[r][7]);
            }
        }
    }

#pragma unroll
    for (int r = 0; r < 4; r++) {
        if (base + r >= N) break;
        int rw = row[r];
        float* hp = g_h + (size_t)rw * HID;
#pragma unroll
        for (int p = 0; p < 8; p++) {
            float2 v = unpack2(acc[r][p]);
            hp[2 * p + 0] = v.x;
            hp[2 * p + 1] = v.y;
        }
    }
}

// ---------------- scale: hs = h * dinv (after join) ---------------------------
__global__ __launch_bounds__(256) void scale_h(int N) {
    int i = blockIdx.x * 256 + threadIdx.x;
    if (i >= N) return;
    float dv = g_dinv[i];
    const float4* hp = (const float4*)(g_h + (size_t)i * HID);
    float4* op = (float4*)(g_hs + (size_t)i * HID);
#pragma unroll
    for (int p = 0; p < 4; p++) {
        float4 v = hp[p];
        v.x *= dv; v.y *= dv; v.z *= dv; v.w *= dv;
        op[p] = v;
    }
}

// ---------------- CSR aggregation: 4 lanes/dst, 2 dst/thread (MLP 16) ---------
// sum into acc over the CSR row of one dst, unrolled 8 (tail helper)
__device__ __forceinline__ void gather8(const float* tbl, const int* cp,
                                        int e, float4& acc) {
    int s0 = cp[e],     s1 = cp[e + 1], s2 = cp[e + 2], s3 = cp[e + 3];
    int s4 = cp[e + 4], s5 = cp[e + 5], s6 = cp[e + 6], s7 = cp[e + 7];
    float4 v0 = *(const float4*)(tbl + (size_t)s0 * HID);
    float4 v1 = *(const float4*)(tbl + (size_t)s1 * HID);
    float4 v2 = *(const float4*)(tbl + (size_t)s2 * HID);
    float4 v3 = *(const float4*)(tbl + (size_t)s3 * HID);
    float4 v4 = *(const float4*)(tbl + (size_t)s4 * HID);
    float4 v5 = *(const float4*)(tbl + (size_t)s5 * HID);
    float4 v6 = *(const float4*)(tbl + (size_t)s6 * HID);
    float4 v7 = *(const float4*)(tbl + (size_t)s7 * HID);
    acc.x += (v0.x + v1.x) + (v2.x + v3.x) + (v4.x + v5.x) + (v6.x + v7.x);
    acc.y += (v0.y + v1.y) + (v2.y + v3.y) + (v4.y + v5.y) + (v6.y + v7.y);
    acc.z += (v0.z + v1.z) + (v2.z + v3.z) + (v4.z + v5.z) + (v6.z + v7.z);
    acc.w += (v0.w + v1.w) + (v2.w + v3.w) + (v4.w + v5.w) + (v6.w + v7.w);
}

template <int LAYER>
__global__ __launch_bounds__(256) void agg_k(const float* __restrict__ b1, int N) {
    const float* src_tbl = (LAYER == 1) ? g_hs : g_ys;
    float*       dst_tbl = (LAYER == 1) ? g_ys : g_hs;

    int t = threadIdx.x;
    int d0 = blockIdx.x * 128 + (t >> 2);
    if (d0 >= N) return;
    int d1 = d0 + 64;
    bool has1 = (d1 < N);
    int part = t & 3;
    const float* tbl = src_tbl + part * 4;

    float4 a0 = *(const float4*)(tbl + (size_t)d0 * HID);   // self-loop d0
    float4 a1 = make_float4(0.f, 0.f, 0.f, 0.f);
    const int* cp0 = g_csr + g_row[d0];
    const int* cp1 = cp0;
    int n0 = g_deg[d0];
    int n1 = 0;
    if (has1) {
        a1 = *(const float4*)(tbl + (size_t)d1 * HID);      // self-loop d1
        cp1 = g_csr + g_row[d1];
        n1 = g_deg[d1];
    }

    // fused main loop: 8 edges of each dst per iteration -> 16 outstanding loads
    int e0 = 0, e1 = 0;
    while (e0 + 8 <= n0 && e1 + 8 <= n1) {
        int s00 = cp0[e0],     s01 = cp0[e0 + 1], s02 = cp0[e0 + 2], s03 = cp0[e0 + 3];
        int s04 = cp0[e0 + 4], s05 = cp0[e0 + 5], s06 = cp0[e0 + 6], s07 = cp0[e0 + 7];
        int s10 = cp1[e1],     s11 = cp1[e1 + 1], s12 = cp1[e1 + 2], s13 = cp1[e1 + 3];
        int s14 = cp1[e1 + 4], s15 = cp1[e1 + 5], s16 = cp1[e1 + 6], s17 = cp1[e1 + 7];
        float4 u0 = *(const float4*)(tbl + (size_t)s00 * HID);
        float4 u1 = *(const float4*)(tbl + (size_t)s01 * HID);
        float4 u2 = *(const float4*)(tbl + (size_t)s02 * HID);
        float4 u3 = *(const float4*)(tbl + (size_t)s03 * HID);
        float4 u4 = *(const float4*)(tbl + (size_t)s04 * HID);
        float4 u5 = *(const float4*)(tbl + (size_t)s05 * HID);
        float4 u6 = *(const float4*)(tbl + (size_t)s06 * HID);
        float4 u7 = *(const float4*)(tbl + (size_t)s07 * HID);
        float4 w0 = *(const float4*)(tbl + (size_t)s10 * HID);
        float4 w1 = *(const float4*)(tbl + (size_t)s11 * HID);
        float4 w2 = *(const float4*)(tbl + (size_t)s12 * HID);
        float4 w3 = *(const float4*)(tbl + (size_t)s13 * HID);
        float4 w4 = *(const float4*)(tbl + (size_t)s14 * HID);
        float4 w5 = *(const float4*)(tbl + (size_t)s15 * HID);
        float4 w6 = *(const float4*)(tbl + (size_t)s16 * HID);
        float4 w7 = *(const float4*)(tbl + (size_t)s17 * HID);
        a0.x += (u0.x + u1.x) + (u2.x + u3.x) + (u4.x + u5.x) + (u6.x + u7.x);
        a0.y += (u0.y + u1.y) + (u2.y + u3.y) + (u4.y + u5.y) + (u6.y + u7.y);
        a0.z += (u0.z + u1.z) + (u2.z + u3.z) + (u4.z + u5.z) + (u6.z + u7.z);
        a0.w += (u0.w + u1.w) + (u2.w + u3.w) + (u4.w + u5.w) + (u6.w + u7.w);
        a1.x += (w0.x + w1.x) + (w2.x + w3.x) + (w4.x + w5.x) + (w6.x + w7.x);
        a1.y += (w0.y + w1.y) + (w2.y + w3.y) + (w4.y + w5.y) + (w6.y + w7.y);
        a1.z += (w0.z + w1.z) + (w2.z + w3.z) + (w4.z + w5.z) + (w6.z + w7.z);
        a1.w += (w0.w + w1.w) + (w2.w + w3.w) + (w4.w + w5.w) + (w6.w + w7.w);
        e0 += 8; e1 += 8;
    }
    // tails
    for (; e0 + 8 <= n0; e0 += 8) gather8(tbl, cp0, e0, a0);
    for (; e0 < n0; e0++) {
        float4 v = *(const float4*)(tbl + (size_t)cp0[e0] * HID);
        a0.x += v.x; a0.y += v.y; a0.z += v.z; a0.w += v.w;
    }
    for (; e1 + 8 <= n1; e1 += 8) gather8(tbl, cp1, e1, a1);
    for (; e1 < n1; e1++) {
        float4 v = *(const float4*)(tbl + (size_t)cp1[e1] * HID);
        a1.x += v.x; a1.y += v.y; a1.z += v.z; a1.w += v.w;
    }

    // epilogue
    if (LAYER == 1) {
        float4 bb = *(const float4*)(b1 + part * 4);
        float dv0 = g_dinv[d0];
        float4 y0;
        y0.x = fmaxf(fmaf(a0.x, dv0, bb.x), 0.0f) * dv0;
        y0.y = fmaxf(fmaf(a0.y, dv0, bb.y), 0.0f) * dv0;
        y0.z = fmaxf(fmaf(a0.z, dv0, bb.z), 0.0f) * dv0;
        y0.w = fmaxf(fmaf(a0.w, dv0, bb.w), 0.0f) * dv0;
        *(float4*)(dst_tbl + (size_t)d0 * HID + part * 4) = y0;
        if (has1) {
            float dv1 = g_dinv[d1];
            float4 y1;
            y1.x = fmaxf(fmaf(a1.x, dv1, bb.x), 0.0f) * dv1;
            y1.y = fmaxf(fmaf(a1.y, dv1, bb.y), 0.0f) * dv1;
            y1.z = fmaxf(fmaf(a1.z, dv1, bb.z), 0.0f) * dv1;
            y1.w = fmaxf(fmaf(a1.w, dv1, bb.w), 0.0f) * dv1;
            *(float4*)(dst_tbl + (size_t)d1 * HID + part * 4) = y1;
        }
    } else {
        float dv0 = g_dinv[d0];
        float4 y0 = make_float4(a0.x * dv0, a0.y * dv0, a0.z * dv0, a0.w * dv0);
        *(float4*)(dst_tbl + (size_t)d0 * HID + part * 4) = y0;
        if (has1) {
            float dv1 = g_dinv[d1];
            float4 y1 = make_float4(a1.x * dv1, a1.y * dv1, a1.z * dv1, a1.w * dv1);
            *(float4*)(dst_tbl + (size_t)d1 * HID + part * 4) = y1;
        }
    }
}

// ---------------- final: logits = a2@W2 + b2 ; log_softmax --------------------
__global__ __launch_bounds__(128) void final_k(const float* __restrict__ W2,
                                               const float* __restrict__ b2,
                                               float* __restrict__ out_lsm,
                                               float* __restrict__ out_logits,
                                               int N, int write_logits) {
    __shared__ float Ws[HID * NC];
    __shared__ float Bs[NC];
    for (int i = threadIdx.x; i < HID * NC; i += 128) Ws[i] = W2[i];
    if (threadIdx.x < NC) Bs[threadIdx.x] = b2[threadIdx.x];
    __syncthreads();

    int node = blockIdx.x * 128 + threadIdx.x;
    if (node >= N) return;

    const float* ap = g_hs + (size_t)node * HID;
    float a[HID];
#pragma unroll
    for (int j = 0; j < HID; j++) a[j] = ap[j];

    float z[NC];
#pragma unroll
    for (int c = 0; c < NC; c++) z[c] = Bs[c];
#pragma unroll
    for (int j = 0; j < HID; j++) {
        float aj = a[j];
#pragma unroll
        for (int c = 0; c < NC; c++) z[c] = fmaf(aj, Ws[j * NC + c], z[c]);
    }

    float m = z[0];
#pragma unroll
    for (int c = 1; c < NC; c++) m = fmaxf(m, z[c]);
    float s = 0.0f;
#pragma unroll
    for (int c = 0; c < NC; c++) s += __expf(z[c] - m);
    float lse = m + __logf(s);

    float* ol = out_lsm + (size_t)node * NC;
#pragma unroll
    for (int c = 0; c < NC; c++) ol[c] = z[c] - lse;
    if (write_logits) {
        float* og = out_logits + (size_t)node * NC;
#pragma unroll
        for (int c = 0; c < NC; c++) og[c] = z[c];
    }
}

// ---------------- launch ------------------------------------------------------
extern "C" void kernel_launch(void* const* d_in, const int* in_sizes, int n_in,
                              void* d_out, int out_size) {
    const float* x  = (const float*)d_in[0];
    const void*  ei = d_in[1];
    const float* W1 = (const float*)d_in[2];
    const float* b1 = (const float*)d_in[3];
    const float* W2 = (const float*)d_in[4];
    const float* b2 = (const float*)d_in[5];

    int E = in_sizes[1] / 2;
    if (E > MAXE) E = MAXE;
    int N = in_sizes[0] / FIN;
    if (N > NN) N = NN;

    float* out = (float*)d_out;
    int write_logits = (out_size >= 2 * N * NC) ? 1 : 0;
    float* out_lsm = out;
    float* out_logits = out + (size_t)N * NC;

    int nb_nodes = (N + 255) / 256;
    int nb_edges = (E + 255) / 256;
    int nb_scan  = (N + SCAN_B - 1) / SCAN_B;
    int nb_agg   = (N + 127) / 128;

    // lazy side-stream setup (created on the uncaptured correctness call)
    static cudaStream_t s2 = 0;
    static cudaEvent_t evF = 0, evJ = 0;
    static int inited = 0;
    if (!inited) {
        if (cudaStreamCreateWithFlags(&s2, cudaStreamNonBlocking) != cudaSuccess) s2 = 0;
        if (s2) {
            if (cudaEventCreateWithFlags(&evF, cudaEventDisableTiming) != cudaSuccess ||
                cudaEventCreateWithFlags(&evJ, cudaEventDisableTiming) != cudaSuccess) {
                s2 = 0;
            }
        }
        inited = 1;
    }
    int fork = (s2 != 0);

    // branch B: dense projection (independent of edge pipeline)
    if (fork) {
        cudaEventRecord(evF, 0);
        cudaStreamWaitEvent(s2, evF, 0);
        gemm1<<<(N + 511) / 512, 128, 0, s2>>>(x, W1, N);
        cudaEventRecord(evJ, s2);
    } else {
        gemm1<<<(N + 511) / 512, 128>>>(x, W1, N);
    }

    // branch A: edge pipeline (default stream)
    init_k<<<nb_nodes, 256>>>((const unsigned int*)ei, E, N);
    count_deg<<<nb_edges, 256>>>(ei, E);
    scan1<<<nb_scan, SCAN_B>>>(N);
    scan2<<<1, 256>>>(nb_scan);
    scan3<<<nb_scan, SCAN_B>>>(N);
    csr_fill<<<nb_edges, 256>>>(ei, E);

    // join
    if (fork) cudaStreamWaitEvent(0, evJ, 0);
    scale_h<<<nb_nodes, 256>>>(N);
    agg_k<1><<<nb_agg, 256>>>(b1, N);
    agg_k<2><<<nb_agg, 256>>>(b1, N);
    final_k<<<(N + 127) / 128, 128>>>(W2, b2, out_lsm, out_logits, N, write_logits);
}

// round 15
// speedup vs baseline: 1.0606x; 1.0606x over previous
#include <cuda_runtime.h>

#define NN  100000      // nodes
#define FIN 512         // input features
#define HID 16          // hidden
#define NC  40          // classes
#define MAXE 4000000    // capacity for edge scratch
#define SCAN_B 512      // elems per scan block

// ---------------- device scratch --------------------------------------------
__device__ int   g_is64;
__device__ int   g_deg [NN];
__device__ int   g_scan[NN];
__device__ int   g_row [NN];
__device__ int   g_cur [NN];
__device__ int   g_bsum[256];
__device__ int   g_bpre[256];
__device__ float g_dinv[NN];
__device__ int   g_csr[MAXE];
__device__ float g_h [(size_t)NN * HID];   // raw x@W1 (side stream)
__device__ float g_hs[(size_t)NN * HID];   // h1*dinv, later a2
__device__ float g_ys[(size_t)NN * HID];   // relu(out1)*dinv

// ---------------- init: zero deg + detect index dtype -------------------------
__global__ __launch_bounds__(256) void init_k(const unsigned int* __restrict__ w,
                                              int E, int N) {
    int i = blockIdx.x * 256 + threadIdx.x;
    if (i < N) g_deg[i] = 0;
    if (blockIdx.x == 0) {
        __shared__ unsigned int sh[256];
        unsigned int acc = 0;
        int n = min(E, 4096);
        for (int j = threadIdx.x; j < n; j += 256) acc |= w[2 * j + 1];
        sh[threadIdx.x] = acc;
        __syncthreads();
        for (int s = 128; s > 0; s >>= 1) {
            if (threadIdx.x < s) sh[threadIdx.x] |= sh[threadIdx.x + s];
            __syncthreads();
        }
        if (threadIdx.x == 0) g_is64 = (sh[0] == 0u) ? 1 : 0;
    }
}

// ---------------- degree count ------------------------------------------------
__global__ __launch_bounds__(256) void count_deg(const void* __restrict__ ei, int E) {
    int e = blockIdx.x * 256 + threadIdx.x;
    if (e >= E) return;
    int d;
    if (g_is64) {
        const long long* p = (const long long*)ei;
        d = (int)p[e + E];
    } else {
        const int* p = (const int*)ei;
        d = p[e + E];
    }
    atomicAdd(&g_deg[d], 1);
}

// ---------------- prefix scan (3 kernels) -------------------------------------
__global__ __launch_bounds__(SCAN_B) void scan1(int N) {
    __shared__ int sh[SCAN_B];
    int gid = blockIdx.x * SCAN_B + threadIdx.x;
    int v = (gid < N) ? g_deg[gid] : 0;
    sh[threadIdx.x] = v;
    __syncthreads();
    for (int off = 1; off < SCAN_B; off <<= 1) {
        int t = (threadIdx.x >= off) ? sh[threadIdx.x - off] : 0;
        __syncthreads();
        sh[threadIdx.x] += t;
        __syncthreads();
    }
    if (gid < N) g_scan[gid] = sh[threadIdx.x];
    if (threadIdx.x == SCAN_B - 1) g_bsum[blockIdx.x] = sh[SCAN_B - 1];
}
__global__ __launch_bounds__(256) void scan2(int nblk) {
    __shared__ int sh[256];
    int v = (threadIdx.x < nblk) ? g_bsum[threadIdx.x] : 0;
    sh[threadIdx.x] = v;
    __syncthreads();
    for (int off = 1; off < 256; off <<= 1) {
        int t = (threadIdx.x >= off) ? sh[threadIdx.x - off] : 0;
        __syncthreads();
        sh[threadIdx.x] += t;
        __syncthreads();
    }
    g_bpre[threadIdx.x] = sh[threadIdx.x] - v;   // exclusive
}
__global__ __launch_bounds__(SCAN_B) void scan3(int N) {
    int gid = blockIdx.x * SCAN_B + threadIdx.x;
    if (gid >= N) return;
    int dg = g_deg[gid];
    int rs = g_scan[gid] - dg + g_bpre[blockIdx.x];
    g_row[gid] = rs;
    g_cur[gid] = rs;
    g_dinv[gid] = rsqrtf((float)(dg + 1));   // +1 self-loop
}

// ---------------- CSR fill ----------------------------------------------------
__global__ __launch_bounds__(256) void csr_fill(const void* __restrict__ ei, int E) {
    int e = blockIdx.x * 256 + threadIdx.x;
    if (e >= E) return;
    int s, d;
    if (g_is64) {
        const long long* p = (const long long*)ei;
        s = (int)p[e];
        d = (int)p[e + E];
    } else {
        const int* p = (const int*)ei;
        s = p[e];
        d = p[e + E];
    }
    int pos = atomicAdd(&g_cur[d], 1);
    g_csr[pos] = s;
}

// ---------------- packed f32x2 helpers ----------------------------------------
__device__ __forceinline__ unsigned long long pack2(float v) {
    unsigned long long r;
    unsigned int u = __float_as_uint(v);
    asm("mov.b64 %0, {%1, %1};" : "=l"(r) : "r"(u));
    return r;
}
__device__ __forceinline__ unsigned long long ffma2(unsigned long long a,
                                                    unsigned long long b,
                                                    unsigned long long c) {
    unsigned long long d;
    asm("fma.rn.f32x2 %0, %1, %2, %3;" : "=l"(d) : "l"(a), "l"(b), "l"(c));
    return d;
}
__device__ __forceinline__ float2 unpack2(unsigned long long v) {
    unsigned int lo, hi;
    asm("mov.b64 {%0, %1}, %2;" : "=r"(lo), "=r"(hi) : "l"(v));
    return make_float2(__uint_as_float(lo), __uint_as_float(hi));
}

// L2-only (cache-global) 16B gather load
__device__ __forceinline__ float4 ldcg4(const float* p) {
    float4 v;
    asm volatile("ld.global.cg.v4.f32 {%0,%1,%2,%3}, [%4];"
                 : "=f"(v.x), "=f"(v.y), "=f"(v.z), "=f"(v.w) : "l"(p));
    return v;
}

// ---------------- GEMM1 (raw): h = x @ W1  (side stream) ----------------------
__global__ __launch_bounds__(128) void gemm1(const float* __restrict__ x,
                                             const float* __restrict__ W1, int N) {
    __shared__ ulonglong2 Ws[FIN * 4];   // 512 x 16 floats = 32KB
    const ulonglong2* Wg = (const ulonglong2*)W1;
    for (int i = threadIdx.x; i < FIN * 4; i += 128) Ws[i] = Wg[i];
    __syncthreads();

    int base = blockIdx.x * 512 + threadIdx.x * 4;
    if (base >= N) return;

    unsigned long long acc[4][8];
#pragma unroll
    for (int r = 0; r < 4; r++)
#pragma unroll
        for (int p = 0; p < 8; p++) acc[r][p] = 0ull;

    int row[4];
    const float* xp[4];
#pragma unroll
    for (int r = 0; r < 4; r++) {
        row[r] = min(base + r, N - 1);
        xp[r] = x + (size_t)row[r] * FIN;
    }

    for (int k = 0; k < FIN; k += 4) {
        float xv[4][4];
#pragma unroll
        for (int r = 0; r < 4; r++)
            *(float4*)xv[r] = *(const float4*)(xp[r] + k);
#pragma unroll
        for (int j = 0; j < 4; j++) {
            ulonglong2 wa = Ws[(k + j) * 4 + 0];
            ulonglong2 wb = Ws[(k + j) * 4 + 1];
            ulonglong2 wc = Ws[(k + j) * 4 + 2];
            ulonglong2 wd = Ws[(k + j) * 4 + 3];
#pragma unroll
            for (int r = 0; r < 4; r++) {
                unsigned long long px = pack2(xv[r][j]);
                acc[r][0] = ffma2(px, wa.x, acc[r][0]);
                acc[r][1] = ffma2(px, wa.y, acc[r][1]);
                acc[r][2] = ffma2(px, wb.x, acc[r][2]);
                acc[r][3] = ffma2(px, wb.y, acc[r][3]);
                acc[r][4] = ffma2(px, wc.x, acc[r][4]);
                acc[r][5] = ffma2(px, wc.y, acc[r][5]);
                acc[r][6] = ffma2(px, wd.x, acc[r][6]);
                acc[r][7] = ffma2(px, wd.y, acc[r][7]);
            }
        }
    }

#pragma unroll
    for (int r = 0; r < 4; r++) {
        if (base + r >= N) break;
        int rw = row[r];
        float* hp = g_h + (size_t)rw * HID;
#pragma unroll
        for (int p = 0; p < 8; p++) {
            float2 v = unpack2(acc[r][p]);
            hp[2 * p + 0] = v.x;
            hp[2 * p + 1] = v.y;
        }
    }
}

// ---------------- scale: hs = h * dinv (after join) ---------------------------
__global__ __launch_bounds__(256) void scale_h(int N) {
    int i = blockIdx.x * 256 + threadIdx.x;
    if (i >= N) return;
    float dv = g_dinv[i];
    const float4* hp = (const float4*)(g_h + (size_t)i * HID);
    float4* op = (float4*)(g_hs + (size_t)i * HID);
#pragma unroll
    for (int p = 0; p < 4; p++) {
        float4 v = hp[p];
        v.x *= dv; v.y *= dv; v.z *= dv; v.w *= dv;
        op[p] = v;
    }
}

// ---------------- CSR aggregation (R6 shape + ldcg + 512-thr blocks) ----------
// Layer 1: ys = relu(dinv*(self + sum) + b1) * dinv
__global__ __launch_bounds__(512) void agg1(const float* __restrict__ b1, int N) {
    int t = threadIdx.x;
    int d = blockIdx.x * 128 + (t >> 2);
    if (d >= N) return;
    int part = t & 3;
    const float* tbl = g_hs + part * 4;

    float4 acc = *(const float4*)(tbl + (size_t)d * HID);   // self-loop
    const int* cp = g_csr + g_row[d];
    int deg = g_deg[d];

    int e = 0;
    int deg8 = deg & ~7;
    for (; e < deg8; e += 8) {
        int s0 = cp[e],     s1 = cp[e + 1], s2 = cp[e + 2], s3 = cp[e + 3];
        int s4 = cp[e + 4], s5 = cp[e + 5], s6 = cp[e + 6], s7 = cp[e + 7];
        float4 v0 = ldcg4(tbl + (size_t)s0 * HID);
        float4 v1 = ldcg4(tbl + (size_t)s1 * HID);
        float4 v2 = ldcg4(tbl + (size_t)s2 * HID);
        float4 v3 = ldcg4(tbl + (size_t)s3 * HID);
        float4 v4 = ldcg4(tbl + (size_t)s4 * HID);
        float4 v5 = ldcg4(tbl + (size_t)s5 * HID);
        float4 v6 = ldcg4(tbl + (size_t)s6 * HID);
        float4 v7 = ldcg4(tbl + (size_t)s7 * HID);
        acc.x += (v0.x + v1.x) + (v2.x + v3.x) + (v4.x + v5.x) + (v6.x + v7.x);
        acc.y += (v0.y + v1.y) + (v2.y + v3.y) + (v4.y + v5.y) + (v6.y + v7.y);
        acc.z += (v0.z + v1.z) + (v2.z + v3.z) + (v4.z + v5.z) + (v6.z + v7.z);
        acc.w += (v0.w + v1.w) + (v2.w + v3.w) + (v4.w + v5.w) + (v6.w + v7.w);
    }
    for (; e < deg; e++) {
        int s = cp[e];
        float4 v = ldcg4(tbl + (size_t)s * HID);
        acc.x += v.x; acc.y += v.y; acc.z += v.z; acc.w += v.w;
    }

    float dv = g_dinv[d];
    float4 bb = *(const float4*)(b1 + part * 4);
    float4 y;
    y.x = fmaxf(fmaf(acc.x, dv, bb.x), 0.0f) * dv;
    y.y = fmaxf(fmaf(acc.y, dv, bb.y), 0.0f) * dv;
    y.z = fmaxf(fmaf(acc.z, dv, bb.z), 0.0f) * dv;
    y.w = fmaxf(fmaf(acc.w, dv, bb.w), 0.0f) * dv;
    *(float4*)(g_ys + (size_t)d * HID + part * 4) = y;
}

// Layer 2: a2 = dinv*(self + sum)  -> g_hs (consumed by final_k)
__global__ __launch_bounds__(512) void agg2(int N) {
    int t = threadIdx.x;
    int d = blockIdx.x * 128 + (t >> 2);
    if (d >= N) return;
    int part = t & 3;
    const float* tbl = g_ys + part * 4;

    float4 acc = *(const float4*)(tbl + (size_t)d * HID);   // self-loop
    const int* cp = g_csr + g_row[d];
    int deg = g_deg[d];

    int e = 0;
    int deg8 = deg & ~7;
    for (; e < deg8; e += 8) {
        int s0 = cp[e],     s1 = cp[e + 1], s2 = cp[e + 2], s3 = cp[e + 3];
        int s4 = cp[e + 4], s5 = cp[e + 5], s6 = cp[e + 6], s7 = cp[e + 7];
        float4 v0 = ldcg4(tbl + (size_t)s0 * HID);
        float4 v1 = ldcg4(tbl + (size_t)s1 * HID);
        float4 v2 = ldcg4(tbl + (size_t)s2 * HID);
        float4 v3 = ldcg4(tbl + (size_t)s3 * HID);
        float4 v4 = ldcg4(tbl + (size_t)s4 * HID);
        float4 v5 = ldcg4(tbl + (size_t)s5 * HID);
        float4 v6 = ldcg4(tbl + (size_t)s6 * HID);
        float4 v7 = ldcg4(tbl + (size_t)s7 * HID);
        acc.x += (v0.x + v1.x) + (v2.x + v3.x) + (v4.x + v5.x) + (v6.x + v7.x);
        acc.y += (v0.y + v1.y) + (v2.y + v3.y) + (v4.y + v5.y) + (v6.y + v7.y);
        acc.z += (v0.z + v1.z) + (v2.z + v3.z) + (v4.z + v5.z) + (v6.z + v7.z);
        acc.w += (v0.w + v1.w) + (v2.w + v3.w) + (v4.w + v5.w) + (v6.w + v7.w);
    }
    for (; e < deg; e++) {
        int s = cp[e];
        float4 v = ldcg4(tbl + (size_t)s * HID);
        acc.x += v.x; acc.y += v.y; acc.z += v.z; acc.w += v.w;
    }

    float dv = g_dinv[d];
    float4 a;
    a.x = acc.x * dv; a.y = acc.y * dv; a.z = acc.z * dv; a.w = acc.w * dv;
    *(float4*)(g_hs + (size_t)d * HID + part * 4) = a;
}

// ---------------- final: logits = a2@W2 + b2 ; log_softmax --------------------
__global__ __launch_bounds__(128) void final_k(const float* __restrict__ W2,
                                               const float* __restrict__ b2,
                                               float* __restrict__ out_lsm,
                                               float* __restrict__ out_logits,
                                               int N, int write_logits) {
    __shared__ float Ws[HID * NC];
    __shared__ float Bs[NC];
    for (int i = threadIdx.x; i < HID * NC; i += 128) Ws[i] = W2[i];
    if (threadIdx.x < NC) Bs[threadIdx.x] = b2[threadIdx.x];
    __syncthreads();

    int node = blockIdx.x * 128 + threadIdx.x;
    if (node >= N) return;

    const float* ap = g_hs + (size_t)node * HID;
    float a[HID];
#pragma unroll
    for (int j = 0; j < HID; j++) a[j] = ap[j];

    float z[NC];
#pragma unroll
    for (int c = 0; c < NC; c++) z[c] = Bs[c];
#pragma unroll
    for (int j = 0; j < HID; j++) {
        float aj = a[j];
#pragma unroll
        for (int c = 0; c < NC; c++) z[c] = fmaf(aj, Ws[j * NC + c], z[c]);
    }

    float m = z[0];
#pragma unroll
    for (int c = 1; c < NC; c++) m = fmaxf(m, z[c]);
    float s = 0.0f;
#pragma unroll
    for (int c = 0; c < NC; c++) s += __expf(z[c] - m);
    float lse = m + __logf(s);

    float* ol = out_lsm + (size_t)node * NC;
#pragma unroll
    for (int c = 0; c < NC; c++) ol[c] = z[c] - lse;
    if (write_logits) {
        float* og = out_logits + (size_t)node * NC;
#pragma unroll
        for (int c = 0; c < NC; c++) og[c] = z[c];
    }
}

// ---------------- launch ------------------------------------------------------
extern "C" void kernel_launch(void* const* d_in, const int* in_sizes, int n_in,
                              void* d_out, int out_size) {
    const float* x  = (const float*)d_in[0];
    const void*  ei = d_in[1];
    const float* W1 = (const float*)d_in[2];
    const float* b1 = (const float*)d_in[3];
    const float* W2 = (const float*)d_in[4];
    const float* b2 = (const float*)d_in[5];

    int E = in_sizes[1] / 2;
    if (E > MAXE) E = MAXE;
    int N = in_sizes[0] / FIN;
    if (N > NN) N = NN;

    float* out = (float*)d_out;
    int write_logits = (out_size >= 2 * N * NC) ? 1 : 0;
    float* out_lsm = out;
    float* out_logits = out + (size_t)N * NC;

    int nb_nodes = (N + 255) / 256;
    int nb_edges = (E + 255) / 256;
    int nb_scan  = (N + SCAN_B - 1) / SCAN_B;
    int nb_agg   = (N + 127) / 128;

    // lazy side-stream setup (created on the uncaptured correctness call)
    static cudaStream_t s2 = 0;
    static cudaEvent_t evF = 0, evJ = 0;
    static int inited = 0;
    if (!inited) {
        if (cudaStreamCreateWithFlags(&s2, cudaStreamNonBlocking) != cudaSuccess) s2 = 0;
        if (s2) {
            if (cudaEventCreateWithFlags(&evF, cudaEventDisableTiming) != cudaSuccess ||
                cudaEventCreateWithFlags(&evJ, cudaEventDisableTiming) != cudaSuccess) {
                s2 = 0;
            }
        }
        inited = 1;
    }
    int fork = (s2 != 0);

    // branch B: dense projection (independent of edge pipeline)
    if (fork) {
        cudaEventRecord(evF, 0);
        cudaStreamWaitEvent(s2, evF, 0);
        gemm1<<<(N + 511) / 512, 128, 0, s2>>>(x, W1, N);
        cudaEventRecord(evJ, s2);
    } else {
        gemm1<<<(N + 511) / 512, 128>>>(x, W1, N);
    }

    // branch A: edge pipeline (default stream)
    init_k<<<nb_nodes, 256>>>((const unsigned int*)ei, E, N);
    count_deg<<<nb_edges, 256>>>(ei, E);
    scan1<<<nb_scan, SCAN_B>>>(N);
    scan2<<<1, 256>>>(nb_scan);
    scan3<<<nb_scan, SCAN_B>>>(N);
    csr_fill<<<nb_edges, 256>>>(ei, E);

    // join
    if (fork) cudaStreamWaitEvent(0, evJ, 0);
    scale_h<<<nb_nodes, 256>>>(N);
    agg1<<<nb_agg, 512>>>(b1, N);
    agg2<<<nb_agg, 512>>>(N);
    final_k<<<(N + 127) / 128, 128>>>(W2, b2, out_lsm, out_logits, N, write_logits);
}

// round 17
// speedup vs baseline: 1.0666x; 1.0057x over previous
#include <cuda_runtime.h>

#define NN  100000      // nodes
#define FIN 512         // input features
#define HID 16          // hidden
#define NC  40          // classes
#define MAXE 4000000    // capacity for edge scratch
#define SCAN_B 512      // elems per scan chunk

// ---------------- device scratch --------------------------------------------
__device__ int   g_is64;
__device__ int   g_deg [NN];
__device__ int   g_row [NN];
__device__ int   g_cur [NN];
__device__ float g_dinv[NN];
__device__ int   g_csr[MAXE];
__device__ unsigned g_total;               // global CSR cursor
__device__ float g_h [(size_t)NN * HID];   // raw x@W1 (side stream)
__device__ float g_hs[(size_t)NN * HID];   // h1*dinv, later a2
__device__ float g_ys[(size_t)NN * HID];   // relu(out1)*dinv

// ---------------- init: zero deg + detect index dtype + zero cursor -----------
__global__ __launch_bounds__(256) void init_k(const unsigned int* __restrict__ w,
                                              int E, int N) {
    int i = blockIdx.x * 256 + threadIdx.x;
    if (i < N) g_deg[i] = 0;
    if (blockIdx.x == 0) {
        __shared__ unsigned int sh[256];
        unsigned int acc = 0;
        int n = min(E, 4096);
        for (int j = threadIdx.x; j < n; j += 256) acc |= w[2 * j + 1];
        sh[threadIdx.x] = acc;
        __syncthreads();
        for (int s = 128; s > 0; s >>= 1) {
            if (threadIdx.x < s) sh[threadIdx.x] |= sh[threadIdx.x + s];
            __syncthreads();
        }
        if (threadIdx.x == 0) {
            g_is64 = (sh[0] == 0u) ? 1 : 0;
            g_total = 0u;
        }
    }
}

// ---------------- degree count ------------------------------------------------
__global__ __launch_bounds__(256) void count_deg(const void* __restrict__ ei, int E) {
    int e = blockIdx.x * 256 + threadIdx.x;
    if (e >= E) return;
    int d;
    if (g_is64) {
        const long long* p = (const long long*)ei;
        d = (int)p[e + E];
    } else {
        const int* p = (const int*)ei;
        d = p[e + E];
    }
    atomicAdd(&g_deg[d], 1);
}

// ---------------- fused scan: per-chunk smem scan + atomic chunk base ---------
// Row offsets need not be node-ordered: each 512-node chunk gets a contiguous
// region whose base comes from one atomicAdd on a global cursor. No cross-CTA
// ordering needed -> single kernel replaces scan1/scan2/scan3.
__global__ __launch_bounds__(SCAN_B) void scan_fused(int N) {
    __shared__ int sh[SCAN_B];
    __shared__ unsigned base;
    int gid = blockIdx.x * SCAN_B + threadIdx.x;
    int dg = (gid < N) ? g_deg[gid] : 0;
    sh[threadIdx.x] = dg;
    __syncthreads();
    for (int off = 1; off < SCAN_B; off <<= 1) {
        int t = (threadIdx.x >= off) ? sh[threadIdx.x - off] : 0;
        __syncthreads();
        sh[threadIdx.x] += t;
        __syncthreads();
    }
    if (threadIdx.x == SCAN_B - 1)
        base = atomicAdd(&g_total, (unsigned)sh[SCAN_B - 1]);
    __syncthreads();
    if (gid < N) {
        int rs = (int)base + sh[threadIdx.x] - dg;   // exclusive within chunk
        g_row[gid] = rs;
        g_cur[gid] = rs;
        g_dinv[gid] = rsqrtf((float)(dg + 1));       // +1 self-loop
    }
}

// ---------------- CSR fill ----------------------------------------------------
__global__ __launch_bounds__(256) void csr_fill(const void* __restrict__ ei, int E) {
    int e = blockIdx.x * 256 + threadIdx.x;
    if (e >= E) return;
    int s, d;
    if (g_is64) {
        const long long* p = (const long long*)ei;
        s = (int)p[e];
        d = (int)p[e + E];
    } else {
        const int* p = (const int*)ei;
        s = p[e];
        d = p[e + E];
    }
    int pos = atomicAdd(&g_cur[d], 1);
    g_csr[pos] = s;
}

// ---------------- packed f32x2 helpers ----------------------------------------
__device__ __forceinline__ unsigned long long pack2(float v) {
    unsigned long long r;
    unsigned int u = __float_as_uint(v);
    asm("mov.b64 %0, {%1, %1};" : "=l"(r) : "r"(u));
    return r;
}
__device__ __forceinline__ unsigned long long ffma2(unsigned long long a,
                                                    unsigned long long b,
                                                    unsigned long long c) {
    unsigned long long d;
    asm("fma.rn.f32x2 %0, %1, %2, %3;" : "=l"(d) : "l"(a), "l"(b), "l"(c));
    return d;
}
__device__ __forceinline__ float2 unpack2(unsigned long long v) {
    unsigned int lo, hi;
    asm("mov.b64 {%0, %1}, %2;" : "=r"(lo), "=r"(hi) : "l"(v));
    return make_float2(__uint_as_float(lo), __uint_as_float(hi));
}

// ---------------- GEMM1 (raw): h = x @ W1  (side stream) ----------------------
__global__ __launch_bounds__(128) void gemm1(const float* __restrict__ x,
                                             const float* __restrict__ W1, int N) {
    __shared__ ulonglong2 Ws[FIN * 4];   // 512 x 16 floats = 32KB
    const ulonglong2* Wg = (const ulonglong2*)W1;
    for (int i = threadIdx.x; i < FIN * 4; i += 128) Ws[i] = Wg[i];
    __syncthreads();

    int base = blockIdx.x * 512 + threadIdx.x * 4;
    if (base >= N) return;

    unsigned long long acc[4][8];
#pragma unroll
    for (int r = 0; r < 4; r++)
#pragma unroll
        for (int p = 0; p < 8; p++) acc[r][p] = 0ull;

    int row[4];
    const float* xp[4];
#pragma unroll
    for (int r = 0; r < 4; r++) {
        row[r] = min(base + r, N - 1);
        xp[r] = x + (size_t)row[r] * FIN;
    }

    for (int k = 0; k < FIN; k += 4) {
        float xv[4][4];
#pragma unroll
        for (int r = 0; r < 4; r++)
            *(float4*)xv[r] = *(const float4*)(xp[r] + k);
#pragma unroll
        for (int j = 0; j < 4; j++) {
            ulonglong2 wa = Ws[(k + j) * 4 + 0];
            ulonglong2 wb = Ws[(k + j) * 4 + 1];
            ulonglong2 wc = Ws[(k + j) * 4 + 2];
            ulonglong2 wd = Ws[(k + j) * 4 + 3];
#pragma unroll
            for (int r = 0; r < 4; r++) {
                unsigned long long px = pack2(xv[r][j]);
                acc[r][0] = ffma2(px, wa.x, acc[r][0]);
                acc[r][1] = ffma2(px, wa.y, acc[r][1]);
                acc[r][2] = ffma2(px, wb.x, acc[r][2]);
                acc[r][3] = ffma2(px, wb.y, acc[r][3]);
                acc[r][4] = ffma2(px, wc.x, acc[r][4]);
                acc[r][5] = ffma2(px, wc.y, acc[r][5]);
                acc[r][6] = ffma2(px, wd.x, acc[r][6]);
                acc[r][7] = ffma2(px, wd.y, acc[r][7]);
            }
        }
    }

#pragma unroll
    for (int r = 0; r < 4; r++) {
        if (base + r >= N) break;
        int rw = row[r];
        float* hp = g_h + (size_t)rw * HID;
#pragma unroll
        for (int p = 0; p < 8; p++) {
            float2 v = unpack2(acc[r][p]);
            hp[2 * p + 0] = v.x;
            hp[2 * p + 1] = v.y;
        }
    }
}

// ---------------- scale: hs = h * dinv (after join) ---------------------------
__global__ __launch_bounds__(256) void scale_h(int N) {
    int i = blockIdx.x * 256 + threadIdx.x;
    if (i >= N) return;
    float dv = g_dinv[i];
    const float4* hp = (const float4*)(g_h + (size_t)i * HID);
    float4* op = (float4*)(g_hs + (size_t)i * HID);
#pragma unroll
    for (int p = 0; p < 4; p++) {
        float4 v = hp[p];
        v.x *= dv; v.y *= dv; v.z *= dv; v.w *= dv;
        op[p] = v;
    }
}

// ---------------- CSR aggregation (R6-winning shape, unchanged) ---------------
// Layer 1: ys = relu(dinv*(self + sum) + b1) * dinv
__global__ __launch_bounds__(256) void agg1(const float* __restrict__ b1, int N) {
    int t = threadIdx.x;
    int d = blockIdx.x * 64 + (t >> 2);
    if (d >= N) return;
    int part = t & 3;
    const float* tbl = g_hs + part * 4;

    float4 acc = *(const float4*)(tbl + (size_t)d * HID);   // self-loop
    const int* cp = g_csr + g_row[d];
    int deg = g_deg[d];

    int e = 0;
    int deg8 = deg & ~7;
    for (; e < deg8; e += 8) {
        int s0 = cp[e],     s1 = cp[e + 1], s2 = cp[e + 2], s3 = cp[e + 3];
        int s4 = cp[e + 4], s5 = cp[e + 5], s6 = cp[e + 6], s7 = cp[e + 7];
        float4 v0 = *(const float4*)(tbl + (size_t)s0 * HID);
        float4 v1 = *(const float4*)(tbl + (size_t)s1 * HID);
        float4 v2 = *(const float4*)(tbl + (size_t)s2 * HID);
        float4 v3 = *(const float4*)(tbl + (size_t)s3 * HID);
        float4 v4 = *(const float4*)(tbl + (size_t)s4 * HID);
        float4 v5 = *(const float4*)(tbl + (size_t)s5 * HID);
        float4 v6 = *(const float4*)(tbl + (size_t)s6 * HID);
        float4 v7 = *(const float4*)(tbl + (size_t)s7 * HID);
        acc.x += (v0.x + v1.x) + (v2.x + v3.x) + (v4.x + v5.x) + (v6.x + v7.x);
        acc.y += (v0.y + v1.y) + (v2.y + v3.y) + (v4.y + v5.y) + (v6.y + v7.y);
        acc.z += (v0.z + v1.z) + (v2.z + v3.z) + (v4.z + v5.z) + (v6.z + v7.z);
        acc.w += (v0.w + v1.w) + (v2.w + v3.w) + (v4.w + v5.w) + (v6.w + v7.w);
    }
    for (; e < deg; e++) {
        int s = cp[e];
        float4 v = *(const float4*)(tbl + (size_t)s * HID);
        acc.x += v.x; acc.y += v.y; acc.z += v.z; acc.w += v.w;
    }

    float dv = g_dinv[d];
    float4 bb = *(const float4*)(b1 + part * 4);
    float4 y;
    y.x = fmaxf(fmaf(acc.x, dv, bb.x), 0.0f) * dv;
    y.y = fmaxf(fmaf(acc.y, dv, bb.y), 0.0f) * dv;
    y.z = fmaxf(fmaf(acc.z, dv, bb.z), 0.0f) * dv;
    y.w = fmaxf(fmaf(acc.w, dv, bb.w), 0.0f) * dv;
    *(float4*)(g_ys + (size_t)d * HID + part * 4) = y;
}

// Layer 2: a2 = dinv*(self + sum)  -> g_hs (consumed by final_k)
__global__ __launch_bounds__(256) void agg2(int N) {
    int t = threadIdx.x;
    int d = blockIdx.x * 64 + (t >> 2);
    if (d >= N) return;
    int part = t & 3;
    const float* tbl = g_ys + part * 4;

    float4 acc = *(const float4*)(tbl + (size_t)d * HID);   // self-loop
    const int* cp = g_csr + g_row[d];
    int deg = g_deg[d];

    int e = 0;
    int deg8 = deg & ~7;
    for (; e < deg8; e += 8) {
        int s0 = cp[e],     s1 = cp[e + 1], s2 = cp[e + 2], s3 = cp[e + 3];
        int s4 = cp[e + 4], s5 = cp[e + 5], s6 = cp[e + 6], s7 = cp[e + 7];
        float4 v0 = *(const float4*)(tbl + (size_t)s0 * HID);
        float4 v1 = *(const float4*)(tbl + (size_t)s1 * HID);
        float4 v2 = *(const float4*)(tbl + (size_t)s2 * HID);
        float4 v3 = *(const float4*)(tbl + (size_t)s3 * HID);
        float4 v4 = *(const float4*)(tbl + (size_t)s4 * HID);
        float4 v5 = *(const float4*)(tbl + (size_t)s5 * HID);
        float4 v6 = *(const float4*)(tbl + (size_t)s6 * HID);
        float4 v7 = *(const float4*)(tbl + (size_t)s7 * HID);
        acc.x += (v0.x + v1.x) + (v2.x + v3.x) + (v4.x + v5.x) + (v6.x + v7.x);
        acc.y += (v0.y + v1.y) + (v2.y + v3.y) + (v4.y + v5.y) + (v6.y + v7.y);
        acc.z += (v0.z + v1.z) + (v2.z + v3.z) + (v4.z + v5.z) + (v6.z + v7.z);
        acc.w += (v0.w + v1.w) + (v2.w + v3.w) + (v4.w + v5.w) + (v6.w + v7.w);
    }
    for (; e < deg; e++) {
        int s = cp[e];
        float4 v = *(const float4*)(tbl + (size_t)s * HID);
        acc.x += v.x; acc.y += v.y; acc.z += v.z; acc.w += v.w;
    }

    float dv = g_dinv[d];
    float4 a;
    a.x = acc.x * dv; a.y = acc.y * dv; a.z = acc.z * dv; a.w = acc.w * dv;
    *(float4*)(g_hs + (size_t)d * HID + part * 4) = a;
}

// ---------------- final: logits = a2@W2 + b2 ; log_softmax --------------------
__global__ __launch_bounds__(128) void final_k(const float* __restrict__ W2,
                                               const float* __restrict__ b2,
                                               float* __restrict__ out_lsm,
                                               float* __restrict__ out_logits,
                                               int N, int write_logits) {
    __shared__ float Ws[HID * NC];
    __shared__ float Bs[NC];
    for (int i = threadIdx.x; i < HID * NC; i += 128) Ws[i] = W2[i];
    if (threadIdx.x < NC) Bs[threadIdx.x] = b2[threadIdx.x];
    __syncthreads();

    int node = blockIdx.x * 128 + threadIdx.x;
    if (node >= N) return;

    const float* ap = g_hs + (size_t)node * HID;
    float a[HID];
#pragma unroll
    for (int j = 0; j < HID; j++) a[j] = ap[j];

    float z[NC];
#pragma unroll
    for (int c = 0; c < NC; c++) z[c] = Bs[c];
#pragma unroll
    for (int j = 0; j < HID; j++) {
        float aj = a[j];
#pragma unroll
        for (int c = 0; c < NC; c++) z[c] = fmaf(aj, Ws[j * NC + c], z[c]);
    }

    float m = z[0];
#pragma unroll
    for (int c = 1; c < NC; c++) m = fmaxf(m, z[c]);
    float s = 0.0f;
#pragma unroll
    for (int c = 0; c < NC; c++) s += __expf(z[c] - m);
    float lse = m + __logf(s);

    float* ol = out_lsm + (size_t)node * NC;
#pragma unroll
    for (int c = 0; c < NC; c++) ol[c] = z[c] - lse;
    if (write_logits) {
        float* og = out_logits + (size_t)node * NC;
#pragma unroll
        for (int c = 0; c < NC; c++) og[c] = z[c];
    }
}

// ---------------- launch ------------------------------------------------------
extern "C" void kernel_launch(void* const* d_in, const int* in_sizes, int n_in,
                              void* d_out, int out_size) {
    const float* x  = (const float*)d_in[0];
    const void*  ei = d_in[1];
    const float* W1 = (const float*)d_in[2];
    const float* b1 = (const float*)d_in[3];
    const float* W2 = (const float*)d_in[4];
    const float* b2 = (const float*)d_in[5];

    int E = in_sizes[1] / 2;
    if (E > MAXE) E = MAXE;
    int N = in_sizes[0] / FIN;
    if (N > NN) N = NN;

    float* out = (float*)d_out;
    int write_logits = (out_size >= 2 * N * NC) ? 1 : 0;
    float* out_lsm = out;
    float* out_logits = out + (size_t)N * NC;

    int nb_nodes = (N + 255) / 256;
    int nb_edges = (E + 255) / 256;
    int nb_scan  = (N + SCAN_B - 1) / SCAN_B;
    int nb_agg   = (N + 63) / 64;

    // lazy side-stream setup (created on the uncaptured correctness call)
    static cudaStream_t s2 = 0;
    static cudaEvent_t evF = 0, evJ = 0;
    static int inited = 0;
    if (!inited) {
        if (cudaStreamCreateWithFlags(&s2, cudaStreamNonBlocking) != cudaSuccess) s2 = 0;
        if (s2) {
            if (cudaEventCreateWithFlags(&evF, cudaEventDisableTiming) != cudaSuccess ||
                cudaEventCreateWithFlags(&evJ, cudaEventDisableTiming) != cudaSuccess) {
                s2 = 0;
            }
        }
        inited = 1;
    }
    int fork = (s2 != 0);

    // branch B: dense projection (independent of edge pipeline)
    if (fork) {
        cudaEventRecord(evF, 0);
        cudaStreamWaitEvent(s2, evF, 0);
        gemm1<<<(N + 511) / 512, 128, 0, s2>>>(x, W1, N);
        cudaEventRecord(evJ, s2);
    } else {
        gemm1<<<(N + 511) / 512, 128>>>(x, W1, N);
    }

    // branch A: edge pipeline (default stream, 4 kernels)
    init_k<<<nb_nodes, 256>>>((const unsigned int*)ei, E, N);
    count_deg<<<nb_edges, 256>>>(ei, E);
    scan_fused<<<nb_scan, SCAN_B>>>(N);
    csr_fill<<<nb_edges, 256>>>(ei, E);

    // join
    if (fork) cudaStreamWaitEvent(0, evJ, 0);
    scale_h<<<nb_nodes, 256>>>(N);
    agg1<<<nb_agg, 256>>>(b1, N);
    agg2<<<nb_agg, 256>>>(N);
    final_k<<<(N + 127) / 128, 128>>>(W2, b2, out_lsm, out_logits, N, write_logits);
}